// round 1
// baseline (speedup 1.0000x reference)
#include <cuda_runtime.h>

#define NB 8
#define NT 4095
#define NS 2048
#define ND 300
#define ND4 75            // ND / 4
#define PAD_IDX 1
#define NCHUNK 64
#define CLEN 32           // NS / NCHUNK

// ---- scratch (static __device__, no allocations) ----
__device__ int   g_leaves[NB * NS];
__device__ __align__(16) float g_prefix[(long)NB * (NS + 1) * ND];  // exclusive prefix, ~19.7 MB
__device__ float g_csum[NB * NCHUNK * ND];
__device__ int   g_lo[NB * NT];
__device__ int   g_h1[NB * NT];     // hi + 1
__device__ float g_inv[NB * NT];    // 1 / max(hi-lo+1, 1)

// ---------------------------------------------------------------------------
// 1) Pack leaves: left-pack tokens with (lo==hi && tok!=PAD) per batch.
//    One block per batch; ballot-based block scan over tiles of 256.
// ---------------------------------------------------------------------------
__global__ void pack_kernel(const int* __restrict__ x, const int* __restrict__ idx) {
    const int b = blockIdx.x;
    const int tid = threadIdx.x;
    const int lane = tid & 31;
    const int w = tid >> 5;
    __shared__ int warp_sums[8];
    __shared__ int s_base;
    if (tid == 0) s_base = 0;
    __syncthreads();

    for (int start = 0; start < NT; start += 256) {
        int t = start + tid;
        int flag = 0;
        int tok = PAD_IDX;
        if (t < NT) {
            tok = x[b * NT + t];
            int lo = idx[(b * NT + t) * 2 + 0];
            int hi = idx[(b * NT + t) * 2 + 1];
            flag = (lo == hi && tok != PAD_IDX) ? 1 : 0;
        }
        unsigned m = __ballot_sync(0xffffffffu, flag);
        int within = __popc(m & ((1u << lane) - 1u));
        if (lane == 0) warp_sums[w] = __popc(m);
        __syncthreads();
        int woff = 0, tot = 0;
        #pragma unroll
        for (int i = 0; i < 8; i++) {
            int ws = warp_sums[i];
            if (i < w) woff += ws;
            tot += ws;
        }
        int pos = s_base + woff + within;
        if (flag && pos < NS) g_leaves[b * NS + pos] = tok;
        __syncthreads();
        if (tid == 0) s_base += tot;
        __syncthreads();
    }
    // fill unfilled tail with PAD (W[PAD] row is zero)
    for (int p = s_base + tid; p < NS; p += 256) g_leaves[b * NS + p] = PAD_IDX;
}

// ---------------------------------------------------------------------------
// 2) Per-(b,t) span metadata: lo, hi+1, 1/denom  (avoids 2.4M MUFU.RCP later)
// ---------------------------------------------------------------------------
__global__ void span_kernel(const int* __restrict__ idx) {
    int i = blockIdx.x * blockDim.x + threadIdx.x;
    if (i >= NB * NT) return;
    int lo = idx[2 * i + 0];
    int hi = idx[2 * i + 1];
    g_lo[i] = lo;
    g_h1[i] = hi + 1;
    int dn = hi - lo + 1;
    if (dn < 1) dn = 1;
    g_inv[i] = 1.0f / (float)dn;
}

// ---------------------------------------------------------------------------
// 3a) Chunk sums: g_csum[b][c][d] = sum over r in chunk c of W[leaf[b][r]][d]
//     grid (NCHUNK, NB), block 320 (300 active lanes over d).
// ---------------------------------------------------------------------------
__global__ void chunksum_kernel(const float* __restrict__ W) {
    const int c = blockIdx.x, b = blockIdx.y;
    const int d = threadIdx.x;
    if (d >= ND) return;
    const int* lv = &g_leaves[b * NS + c * CLEN];
    int leaf[CLEN];
    #pragma unroll
    for (int r = 0; r < CLEN; r++) leaf[r] = lv[r];
    float a0 = 0.f, a1 = 0.f, a2 = 0.f, a3 = 0.f;
    #pragma unroll
    for (int r = 0; r < CLEN; r += 4) {
        a0 += __ldg(W + (long)leaf[r + 0] * ND + d);
        a1 += __ldg(W + (long)leaf[r + 1] * ND + d);
        a2 += __ldg(W + (long)leaf[r + 2] * ND + d);
        a3 += __ldg(W + (long)leaf[r + 3] * ND + d);
    }
    g_csum[(b * NCHUNK + c) * ND + d] = (a0 + a1) + (a2 + a3);
}

// ---------------------------------------------------------------------------
// 3b) Scan chunk sums in place -> exclusive chunk offsets. One thread per (b,d).
// ---------------------------------------------------------------------------
__global__ void chunkscan_kernel() {
    int i = blockIdx.x * blockDim.x + threadIdx.x;
    if (i >= NB * ND) return;
    int b = i / ND, d = i - b * ND;
    float acc = 0.f;
    #pragma unroll 8
    for (int c = 0; c < NCHUNK; c++) {
        float* p = &g_csum[(b * NCHUNK + c) * ND + d];
        float v = *p;
        *p = acc;
        acc += v;
    }
}

// ---------------------------------------------------------------------------
// 3c) Write exclusive prefix P[b][r][d]; last chunk also writes P[b][S][d].
// ---------------------------------------------------------------------------
__global__ void prefix_kernel(const float* __restrict__ W) {
    const int c = blockIdx.x, b = blockIdx.y;
    const int d = threadIdx.x;
    if (d >= ND) return;
    const int* lv = &g_leaves[b * NS + c * CLEN];
    int leaf[CLEN];
    #pragma unroll
    for (int r = 0; r < CLEN; r++) leaf[r] = lv[r];
    float v[CLEN];
    #pragma unroll
    for (int r = 0; r < CLEN; r++) v[r] = __ldg(W + (long)leaf[r] * ND + d);

    float acc = g_csum[(b * NCHUNK + c) * ND + d];
    float* P = &g_prefix[((long)b * (NS + 1) + (long)c * CLEN) * ND + d];
    #pragma unroll
    for (int r = 0; r < CLEN; r++) {
        P[(long)r * ND] = acc;
        acc += v[r];
    }
    if (c == NCHUNK - 1) P[(long)CLEN * ND] = acc;   // P[b][S][d]
}

// ---------------------------------------------------------------------------
// 4) Query: out[b][t] = (P[hi+1] - P[lo]) * inv.  float4-vectorized over d.
// ---------------------------------------------------------------------------
__global__ void out_kernel(float4* __restrict__ out) {
    const float4* __restrict__ P4 = (const float4*)g_prefix;
    int idx = blockIdx.x * blockDim.x + threadIdx.x;
    if (idx >= NB * NT * ND4) return;
    int bt = idx / ND4;
    int j = idx - bt * ND4;
    int b = bt / NT;
    int lo = g_lo[bt];
    int h1 = g_h1[bt];
    float inv = g_inv[bt];
    long base = (long)b * (NS + 1) * ND4;
    float4 a = __ldg(&P4[base + (long)h1 * ND4 + j]);
    float4 c = __ldg(&P4[base + (long)lo * ND4 + j]);
    float4 o;
    o.x = (a.x - c.x) * inv;
    o.y = (a.y - c.y) * inv;
    o.z = (a.z - c.z) * inv;
    o.w = (a.w - c.w) * inv;
    out[idx] = o;
}

// ---------------------------------------------------------------------------
extern "C" void kernel_launch(void* const* d_in, const int* in_sizes, int n_in,
                              void* d_out, int out_size) {
    const int*   x   = (const int*)d_in[0];     // [B,T]   int32
    const int*   idx = (const int*)d_in[1];     // [B,T,2] int32
    const float* W   = (const float*)d_in[2];   // [V,D]   fp32
    float* out = (float*)d_out;                 // [B,T,D] fp32

    pack_kernel<<<NB, 256>>>(x, idx);
    span_kernel<<<(NB * NT + 255) / 256, 256>>>(idx);

    dim3 gscan(NCHUNK, NB);
    chunksum_kernel<<<gscan, 320>>>(W);
    chunkscan_kernel<<<(NB * ND + 255) / 256, 256>>>();
    prefix_kernel<<<gscan, 320>>>(W);

    int n4 = NB * NT * ND4;
    out_kernel<<<(n4 + 255) / 256, 256>>>((float4*)out);
}

// round 2
// speedup vs baseline: 1.1684x; 1.1684x over previous
#include <cuda_runtime.h>

#define NB 8
#define NT 4095
#define NS 2048
#define ND 300
#define ND4 75            // ND / 4
#define PAD_IDX 1
#define NCHUNK 64
#define CLEN 32           // NS / NCHUNK

// ---- scratch (static __device__, no allocations) ----
__device__ int   g_leaves[NB * NS];
__device__ __align__(16) float g_prefix[(long)NB * (NS + 1) * ND];  // exclusive prefix, ~19.7 MB
__device__ float g_csum[NB * NCHUNK * ND];

// ---------------------------------------------------------------------------
// 1) Pack leaves: left-pack tokens with (lo==hi && tok!=PAD) per batch.
//    One block (1024 threads) per batch; ballot-based block scan, 4 tiles.
// ---------------------------------------------------------------------------
__global__ void pack_kernel(const int* __restrict__ x, const int* __restrict__ idx) {
    const int b = blockIdx.x;
    const int tid = threadIdx.x;
    const int lane = tid & 31;
    const int w = tid >> 5;
    __shared__ int warp_sums[32];
    __shared__ int s_base;
    if (tid == 0) s_base = 0;
    __syncthreads();

    #pragma unroll
    for (int start = 0; start < 4096; start += 1024) {
        int t = start + tid;
        int flag = 0;
        int tok = PAD_IDX;
        if (t < NT) {
            tok = x[b * NT + t];
            int lo = idx[(b * NT + t) * 2 + 0];
            int hi = idx[(b * NT + t) * 2 + 1];
            flag = (lo == hi && tok != PAD_IDX) ? 1 : 0;
        }
        unsigned m = __ballot_sync(0xffffffffu, flag);
        int within = __popc(m & ((1u << lane) - 1u));
        if (lane == 0) warp_sums[w] = __popc(m);
        __syncthreads();
        int woff = 0, tot = 0;
        #pragma unroll
        for (int i = 0; i < 32; i++) {
            int ws = warp_sums[i];
            if (i < w) woff += ws;
            tot += ws;
        }
        int pos = s_base + woff + within;
        if (flag && pos < NS) g_leaves[b * NS + pos] = tok;
        __syncthreads();
        if (tid == 0) s_base += tot;
        __syncthreads();
    }
    // fill unfilled tail with PAD (W[PAD] row is zero)
    for (int p = s_base + tid; p < NS; p += 1024) g_leaves[b * NS + p] = PAD_IDX;
}

// ---------------------------------------------------------------------------
// 2a) Chunk sums: g_csum[b][c][d] = sum over r in chunk c of W[leaf[b][r]][d]
//     grid (NCHUNK, NB), block 320 (300 active lanes over d).
// ---------------------------------------------------------------------------
__global__ void chunksum_kernel(const float* __restrict__ W) {
    const int c = blockIdx.x, b = blockIdx.y;
    const int d = threadIdx.x;
    if (d >= ND) return;
    const int* lv = &g_leaves[b * NS + c * CLEN];
    int leaf[CLEN];
    #pragma unroll
    for (int r = 0; r < CLEN; r++) leaf[r] = lv[r];
    float a0 = 0.f, a1 = 0.f, a2 = 0.f, a3 = 0.f;
    #pragma unroll
    for (int r = 0; r < CLEN; r += 4) {
        a0 += __ldg(W + (long)leaf[r + 0] * ND + d);
        a1 += __ldg(W + (long)leaf[r + 1] * ND + d);
        a2 += __ldg(W + (long)leaf[r + 2] * ND + d);
        a3 += __ldg(W + (long)leaf[r + 3] * ND + d);
    }
    g_csum[(b * NCHUNK + c) * ND + d] = (a0 + a1) + (a2 + a3);
}

// ---------------------------------------------------------------------------
// 2b) Scan chunk sums in place -> exclusive chunk offsets.
//     One WARP per (b,d): lane holds chunks (2*lane, 2*lane+1), shfl scan.
// ---------------------------------------------------------------------------
__global__ void chunkscan_kernel() {
    int gw = (blockIdx.x * blockDim.x + threadIdx.x) >> 5;   // global warp id
    int lane = threadIdx.x & 31;
    if (gw >= NB * ND) return;
    int b = gw / ND, d = gw - b * ND;

    float* base = &g_csum[b * NCHUNK * ND + d];
    float v0 = base[(2 * lane + 0) * ND];
    float v1 = base[(2 * lane + 1) * ND];
    float s = v0 + v1;

    // inclusive warp scan of s
    float incl = s;
    #pragma unroll
    for (int off = 1; off < 32; off <<= 1) {
        float n = __shfl_up_sync(0xffffffffu, incl, off);
        if (lane >= off) incl += n;
    }
    float excl = incl - s;
    base[(2 * lane + 0) * ND] = excl;
    base[(2 * lane + 1) * ND] = excl + v0;
}

// ---------------------------------------------------------------------------
// 2c) Write exclusive prefix P[b][r][d]; last chunk also writes P[b][S][d].
// ---------------------------------------------------------------------------
__global__ void prefix_kernel(const float* __restrict__ W) {
    const int c = blockIdx.x, b = blockIdx.y;
    const int d = threadIdx.x;
    if (d >= ND) return;
    const int* lv = &g_leaves[b * NS + c * CLEN];
    int leaf[CLEN];
    #pragma unroll
    for (int r = 0; r < CLEN; r++) leaf[r] = lv[r];
    float v[CLEN];
    #pragma unroll
    for (int r = 0; r < CLEN; r++) v[r] = __ldg(W + (long)leaf[r] * ND + d);

    float acc = g_csum[(b * NCHUNK + c) * ND + d];
    float* P = &g_prefix[((long)b * (NS + 1) + (long)c * CLEN) * ND + d];
    #pragma unroll
    for (int r = 0; r < CLEN; r++) {
        P[(long)r * ND] = acc;
        acc += v[r];
    }
    if (c == NCHUNK - 1) P[(long)CLEN * ND] = acc;   // P[b][S][d]
}

// ---------------------------------------------------------------------------
// 3) Query: out[b][t] = (P[hi+1] - P[lo]) / denom.  float4 over d, metadata
//    read inline from idx (same-address within warp -> L1 broadcast).
// ---------------------------------------------------------------------------
__global__ void out_kernel(const int* __restrict__ idxp, float4* __restrict__ out) {
    const float4* __restrict__ P4 = (const float4*)g_prefix;
    int i = blockIdx.x * blockDim.x + threadIdx.x;
    if (i >= NB * NT * ND4) return;
    int bt = i / ND4;
    int j = i - bt * ND4;
    int b = bt / NT;
    int lo = idxp[2 * bt + 0];
    int hi = idxp[2 * bt + 1];
    int dn = hi - lo + 1;
    if (dn < 1) dn = 1;
    float inv = 1.0f / (float)dn;
    long base = (long)b * (NS + 1) * ND4;
    float4 a = __ldg(&P4[base + (long)(hi + 1) * ND4 + j]);
    float4 c = __ldg(&P4[base + (long)lo * ND4 + j]);
    float4 o;
    o.x = (a.x - c.x) * inv;
    o.y = (a.y - c.y) * inv;
    o.z = (a.z - c.z) * inv;
    o.w = (a.w - c.w) * inv;
    out[i] = o;
}

// ---------------------------------------------------------------------------
extern "C" void kernel_launch(void* const* d_in, const int* in_sizes, int n_in,
                              void* d_out, int out_size) {
    const int*   x   = (const int*)d_in[0];     // [B,T]   int32
    const int*   idx = (const int*)d_in[1];     // [B,T,2] int32
    const float* W   = (const float*)d_in[2];   // [V,D]   fp32
    float* out = (float*)d_out;                 // [B,T,D] fp32

    pack_kernel<<<NB, 1024>>>(x, idx);

    dim3 gscan(NCHUNK, NB);
    chunksum_kernel<<<gscan, 320>>>(W);

    int nwarp = NB * ND;                         // 2400 warps
    chunkscan_kernel<<<(nwarp * 32 + 255) / 256, 256>>>();

    prefix_kernel<<<gscan, 320>>>(W);

    int n4 = NB * NT * ND4;
    out_kernel<<<(n4 + 255) / 256, 256>>>(idx, (float4*)out);
}

// round 3
// speedup vs baseline: 1.1714x; 1.0026x over previous
#include <cuda_runtime.h>

#define NB 8
#define NT 4095
#define NS 2048
#define ND 300
#define ND4 75            // ND / 4
#define PAD_IDX 1
#define NCHUNK 64
#define CLEN 32           // NS / NCHUNK

// ---- scratch (static __device__, no allocations) ----
__device__ int   g_leaves[NB * NS];
__device__ __align__(16) float g_prefix[(long)NB * (NS + 1) * ND];  // exclusive prefix, ~19.7 MB
__device__ __align__(16) float g_csum[NB * NCHUNK * ND];

// ---------------------------------------------------------------------------
// 1) Pack leaves: left-pack tokens with (lo==hi && tok!=PAD) per batch.
//    One block (1024 threads) per batch; ballot-based block scan, 4 tiles.
// ---------------------------------------------------------------------------
__global__ void pack_kernel(const int* __restrict__ x, const int2* __restrict__ idx) {
    const int b = blockIdx.x;
    const int tid = threadIdx.x;
    const int lane = tid & 31;
    const int w = tid >> 5;
    __shared__ int warp_sums[32];
    __shared__ int s_base;
    if (tid == 0) s_base = 0;
    __syncthreads();

    #pragma unroll
    for (int start = 0; start < 4096; start += 1024) {
        int t = start + tid;
        int flag = 0;
        int tok = PAD_IDX;
        if (t < NT) {
            tok = x[b * NT + t];
            int2 lh = idx[b * NT + t];
            flag = (lh.x == lh.y && tok != PAD_IDX) ? 1 : 0;
        }
        unsigned m = __ballot_sync(0xffffffffu, flag);
        int within = __popc(m & ((1u << lane) - 1u));
        if (lane == 0) warp_sums[w] = __popc(m);
        __syncthreads();
        int woff = 0, tot = 0;
        #pragma unroll
        for (int i = 0; i < 32; i++) {
            int ws = warp_sums[i];
            if (i < w) woff += ws;
            tot += ws;
        }
        int pos = s_base + woff + within;
        if (flag && pos < NS) g_leaves[b * NS + pos] = tok;
        __syncthreads();
        if (tid == 0) s_base += tot;
        __syncthreads();
    }
    // fill unfilled tail with PAD (W[PAD] row is zero)
    for (int p = s_base + tid; p < NS; p += 1024) g_leaves[b * NS + p] = PAD_IDX;
}

// ---------------------------------------------------------------------------
// 2a) Chunk sums (float4 over d): g_csum[b][c][:] = sum_{r in chunk} W[leaf]
//     grid (NCHUNK/4, NB), block (75, 4): ty selects chunk, tx = float4 lane.
// ---------------------------------------------------------------------------
__global__ __launch_bounds__(300) void chunksum_kernel(const float4* __restrict__ W4) {
    const int c = blockIdx.x * 4 + threadIdx.y;
    const int b = blockIdx.y;
    const int j = threadIdx.x;                 // 0..74
    const int* lv = &g_leaves[b * NS + c * CLEN];
    int leaf[CLEN];
    #pragma unroll
    for (int r = 0; r < CLEN; r++) leaf[r] = lv[r];

    float4 a0 = {0,0,0,0}, a1 = {0,0,0,0}, a2 = {0,0,0,0}, a3 = {0,0,0,0};
    #pragma unroll
    for (int r = 0; r < CLEN; r += 4) {
        float4 v0 = __ldg(&W4[(long)leaf[r + 0] * ND4 + j]);
        float4 v1 = __ldg(&W4[(long)leaf[r + 1] * ND4 + j]);
        float4 v2 = __ldg(&W4[(long)leaf[r + 2] * ND4 + j]);
        float4 v3 = __ldg(&W4[(long)leaf[r + 3] * ND4 + j]);
        a0.x += v0.x; a0.y += v0.y; a0.z += v0.z; a0.w += v0.w;
        a1.x += v1.x; a1.y += v1.y; a1.z += v1.z; a1.w += v1.w;
        a2.x += v2.x; a2.y += v2.y; a2.z += v2.z; a2.w += v2.w;
        a3.x += v3.x; a3.y += v3.y; a3.z += v3.z; a3.w += v3.w;
    }
    float4 s;
    s.x = (a0.x + a1.x) + (a2.x + a3.x);
    s.y = (a0.y + a1.y) + (a2.y + a3.y);
    s.z = (a0.z + a1.z) + (a2.z + a3.z);
    s.w = (a0.w + a1.w) + (a2.w + a3.w);
    ((float4*)g_csum)[(b * NCHUNK + c) * ND4 + j] = s;
}

// ---------------------------------------------------------------------------
// 2b) Scan chunk sums in place -> exclusive chunk offsets.
//     One WARP per (b,d): lane holds chunks (2*lane, 2*lane+1), shfl scan.
// ---------------------------------------------------------------------------
__global__ void chunkscan_kernel() {
    int gw = (blockIdx.x * blockDim.x + threadIdx.x) >> 5;   // global warp id
    int lane = threadIdx.x & 31;
    if (gw >= NB * ND) return;
    int b = gw / ND, d = gw - b * ND;

    float* base = &g_csum[b * NCHUNK * ND + d];
    float v0 = base[(2 * lane + 0) * ND];
    float v1 = base[(2 * lane + 1) * ND];
    float s = v0 + v1;

    float incl = s;
    #pragma unroll
    for (int off = 1; off < 32; off <<= 1) {
        float n = __shfl_up_sync(0xffffffffu, incl, off);
        if (lane >= off) incl += n;
    }
    float excl = incl - s;
    base[(2 * lane + 0) * ND] = excl;
    base[(2 * lane + 1) * ND] = excl + v0;
}

// ---------------------------------------------------------------------------
// 2c) Exclusive prefix P[b][r][:] (float4 over d); last chunk writes P[b][S].
//     grid (NCHUNK/4, NB), block (75, 4).
// ---------------------------------------------------------------------------
__global__ __launch_bounds__(300) void prefix_kernel(const float4* __restrict__ W4) {
    const int c = blockIdx.x * 4 + threadIdx.y;
    const int b = blockIdx.y;
    const int j = threadIdx.x;                 // 0..74
    const int* lv = &g_leaves[b * NS + c * CLEN];
    int leaf[CLEN];
    #pragma unroll
    for (int r = 0; r < CLEN; r++) leaf[r] = lv[r];

    float4 acc = ((const float4*)g_csum)[(b * NCHUNK + c) * ND4 + j];
    float4* P = &((float4*)g_prefix)[((long)b * (NS + 1) + (long)c * CLEN) * ND4 + j];

    #pragma unroll
    for (int r = 0; r < CLEN; r += 4) {
        float4 v0 = __ldg(&W4[(long)leaf[r + 0] * ND4 + j]);
        float4 v1 = __ldg(&W4[(long)leaf[r + 1] * ND4 + j]);
        float4 v2 = __ldg(&W4[(long)leaf[r + 2] * ND4 + j]);
        float4 v3 = __ldg(&W4[(long)leaf[r + 3] * ND4 + j]);
        P[(long)(r + 0) * ND4] = acc;
        acc.x += v0.x; acc.y += v0.y; acc.z += v0.z; acc.w += v0.w;
        P[(long)(r + 1) * ND4] = acc;
        acc.x += v1.x; acc.y += v1.y; acc.z += v1.z; acc.w += v1.w;
        P[(long)(r + 2) * ND4] = acc;
        acc.x += v2.x; acc.y += v2.y; acc.z += v2.z; acc.w += v2.w;
        P[(long)(r + 3) * ND4] = acc;
        acc.x += v3.x; acc.y += v3.y; acc.z += v3.z; acc.w += v3.w;
    }
    if (c == NCHUNK - 1) P[(long)CLEN * ND4] = acc;   // P[b][S][:]
}

// ---------------------------------------------------------------------------
// 3) Query: out[b][t] = (P[hi+1] - P[lo]) / denom.  float4 over d.
// ---------------------------------------------------------------------------
__global__ void out_kernel(const int2* __restrict__ idxp, float4* __restrict__ out) {
    const float4* __restrict__ P4 = (const float4*)g_prefix;
    int i = blockIdx.x * blockDim.x + threadIdx.x;
    if (i >= NB * NT * ND4) return;
    int bt = i / ND4;
    int j = i - bt * ND4;
    int b = bt / NT;
    int2 lh = idxp[bt];
    int dn = lh.y - lh.x + 1;
    if (dn < 1) dn = 1;
    float inv = 1.0f / (float)dn;
    long base = (long)b * (NS + 1) * ND4;
    float4 a = __ldg(&P4[base + (long)(lh.y + 1) * ND4 + j]);
    float4 c = __ldg(&P4[base + (long)lh.x * ND4 + j]);
    float4 o;
    o.x = (a.x - c.x) * inv;
    o.y = (a.y - c.y) * inv;
    o.z = (a.z - c.z) * inv;
    o.w = (a.w - c.w) * inv;
    out[i] = o;
}

// ---------------------------------------------------------------------------
extern "C" void kernel_launch(void* const* d_in, const int* in_sizes, int n_in,
                              void* d_out, int out_size) {
    const int*  x   = (const int*)d_in[0];      // [B,T]   int32
    const int2* idx = (const int2*)d_in[1];     // [B,T,2] int32
    const float4* W4 = (const float4*)d_in[2];  // [V,D]   fp32
    float* out = (float*)d_out;                 // [B,T,D] fp32

    pack_kernel<<<NB, 1024>>>(x, idx);

    dim3 blk(75, 4);
    dim3 gscan(NCHUNK / 4, NB);
    chunksum_kernel<<<gscan, blk>>>(W4);

    int nwarp = NB * ND;                         // 2400 warps
    chunkscan_kernel<<<(nwarp * 32 + 255) / 256, 256>>>();

    prefix_kernel<<<gscan, blk>>>(W4);

    int n4 = NB * NT * ND4;
    out_kernel<<<(n4 + 255) / 256, 256>>>(idx, (float4*)out);
}